// round 1
// baseline (speedup 1.0000x reference)
#include <cuda_runtime.h>
#include <math.h>

#define BB 4
#define HH 512
#define WW 512
#define NPIX (BB*HH*WW)

static __device__ __constant__ float TAU   = 0.01f;
static __device__ __constant__ float RHO   = 1.99f;
static __device__ __constant__ float SIGMA = 1.3888888888888888f; // 1/0.01/72

// Persistent state + scratch (allocation-free)
__device__ float  g_x2 [NPIX];
__device__ float2 g_r2 [NPIX];
__device__ float4 g_u2 [NPIX];
__device__ float2 g_tmp[NPIX];
__device__ float  g_xbar[NPIX];
__device__ float2 g_rbar[NPIX];
__device__ float2 g_v  [NPIX];

__global__ void k_init(const float* __restrict__ y) {
    int i = blockIdx.x * blockDim.x + threadIdx.x;
    if (i < NPIX) {
        g_x2[i] = y[i];
        g_r2[i] = make_float2(0.f, 0.f);
        g_u2[i] = make_float4(0.f, 0.f, 0.f, 0.f);
    }
}

// Pass 1: tmp = TAU * epsilon2_adjoint(u2)
__global__ void k_tmp() {
    int w = blockIdx.x * blockDim.x + threadIdx.x;
    int h = blockIdx.y * blockDim.y + threadIdx.y;
    int b = blockIdx.z;
    int i = (b * HH + h) * WW + w;

    float4 c = g_u2[i];                                   // G0,G1,G2,G3 at (h,w)
    float G0d = (h < HH-1) ? g_u2[i + WW].x : 0.f;        // G0[h+1,w]
    float G3u = (h > 0)    ? g_u2[i - WW].w : 0.f;        // G3[h-1,w]
    float G1r = 0.f, G2r = 0.f;
    if (w < WW-1) { float4 r = g_u2[i + 1]; G1r = r.y; G2r = r.z; }

    // I0 = G0 - G0[h+1,w] - G1[h,w+1] + G1[h,w]*(w>0)
    float t0 = c.x - G0d - G1r + ((w > 0) ? c.y : 0.f);
    // I1 = G2 - G2[h,w+1] - G3*(h<H-1) + G3[h-1,w]
    float t1 = c.z - G2r - ((h < HH-1) ? c.w : 0.f) + G3u;

    g_tmp[i] = make_float2(TAU * t0, TAU * t1);
}

// Pass 2: x-prox + relaxation (-> xbar, x2), r-prox + relaxation (-> rbar, r2)
__global__ void k_xr(const float* __restrict__ y, const int* __restrict__ ths,
                     float* __restrict__ x2_out_last) {
    int w = blockIdx.x * blockDim.x + threadIdx.x;
    int h = blockIdx.y * blockDim.y + threadIdx.y;
    int b = blockIdx.z;
    int i = (b * HH + h) * WW + w;

    float2 tc = g_tmp[i];

    // nabla2_adjoint(tmp)
    float div = 0.f;
    if (w < WW-1) div -= tc.x;
    if (w > 0)    div += g_tmp[i - 1].x;
    if (h < HH-1) div -= tc.y;
    if (h > 0)    div += g_tmp[i - WW].y;

    float x2o = g_x2[i];
    float x = (x2o - div + TAU * y[i]) * (1.f / (1.f + TAU));

    g_xbar[i] = 2.f * x - x2o;
    float x2n = x2o + RHO * (x - x2o);
    if (x2_out_last) x2_out_last[i] = x2n;
    else             g_x2[i]        = x2n;

    // r update
    float lam1 = 0.1f * (float)ths[0];
    float2 r2o = g_r2[i];
    float rvx = r2o.x + tc.x;
    float rvy = r2o.y + tc.y;
    float nrm = sqrtf(rvx * rvx + rvy * rvy);
    float left = nrm * (1.f / (TAU * lam1));
    float s = 1.f - 1.f / fmaxf(left, 1.f);
    float rx = rvx * s, ry = rvy * s;

    g_rbar[i] = make_float2(2.f * rx - r2o.x, 2.f * ry - r2o.y);
    g_r2[i]   = make_float2(r2o.x + RHO * (rx - r2o.x),
                            r2o.y + RHO * (ry - r2o.y));
}

// Pass 3: v = nabla2(xbar) - rbar
__global__ void k_v() {
    int w = blockIdx.x * blockDim.x + threadIdx.x;
    int h = blockIdx.y * blockDim.y + threadIdx.y;
    int b = blockIdx.z;
    int i = (b * HH + h) * WW + w;

    float xb = g_xbar[i];
    float2 rb = g_rbar[i];
    float v0 = ((w < WW-1) ? (g_xbar[i + 1]  - xb) : 0.f) - rb.x;
    float v1 = ((h < HH-1) ? (g_xbar[i + WW] - xb) : 0.f) - rb.y;
    g_v[i] = make_float2(v0, v1);
}

// Pass 4: u = prox_sigma_g_conj(u2 + SIGMA*epsilon2(v)); u2 += RHO*(u - u2)
__global__ void k_u(const int* __restrict__ ths) {
    int w = blockIdx.x * blockDim.x + threadIdx.x;
    int h = blockIdx.y * blockDim.y + threadIdx.y;
    int b = blockIdx.z;
    int i = (b * HH + h) * WW + w;

    float2 vc = g_v[i];
    float I0u = (h > 0)    ? g_v[i - WW].x : 0.f;
    float I1d = (h < HH-1) ? g_v[i + WW].y : 0.f;
    float2 vl = (w > 0) ? g_v[i - 1] : make_float2(0.f, 0.f);

    float G0 = vc.x - I0u;
    float G1 = (w > 0) ? (vc.x - vl.x) : 0.f;
    float G2 = vc.y - ((w > 0) ? vl.y : 0.f);
    float G3 = (h < HH-1) ? (I1d - vc.y) : 0.f;

    float4 u2o = g_u2[i];
    float u0 = u2o.x + SIGMA * G0;
    float u1 = u2o.y + SIGMA * G1;
    float u2c = u2o.z + SIGMA * G2;
    float u3 = u2o.w + SIGMA * G3;

    float lam2 = 0.15f * (float)ths[0];
    float nrm = sqrtf(u0*u0 + u1*u1 + u2c*u2c + u3*u3);
    float sc = 1.f / fmaxf(nrm * (1.f / lam2), 1.f);
    u0 *= sc; u1 *= sc; u2c *= sc; u3 *= sc;

    g_u2[i] = make_float4(u2o.x + RHO * (u0  - u2o.x),
                          u2o.y + RHO * (u1  - u2o.y),
                          u2o.z + RHO * (u2c - u2o.z),
                          u2o.w + RHO * (u3  - u2o.w));
}

extern "C" void kernel_launch(void* const* d_in, const int* in_sizes, int n_in,
                              void* d_out, int out_size) {
    const float* y   = (const float*)d_in[0];
    const int*   ths = (const int*)d_in[1];
    float*       out = (float*)d_out;

    dim3 blk(32, 8, 1);
    dim3 grd(WW / 32, HH / 8, BB);

    k_init<<<(NPIX + 255) / 256, 256>>>(y);

    const int N_IT = 10;
    for (int it = 0; it < N_IT; ++it) {
        bool last = (it == N_IT - 1);
        k_tmp<<<grd, blk>>>();
        k_xr<<<grd, blk>>>(y, ths, last ? out : nullptr);
        if (!last) {
            k_v<<<grd, blk>>>();
            k_u<<<grd, blk>>>(ths);
        }
    }
}

// round 2
// speedup vs baseline: 1.0886x; 1.0886x over previous
#include <cuda_runtime.h>
#include <math.h>

#define BB 4
#define HH 512
#define WW 512
#define NPIX (BB*HH*WW)
#define TW 32
#define TH 8

#define TAUc   0.01f
#define RHOc   1.99f
#define SIGMAc 1.3888888888888888f   // 1/0.01/72

// Persistent state + scratch (allocation-free)
__device__ float  g_x2  [NPIX];
__device__ float2 g_r2  [NPIX];
__device__ float4 g_u2  [NPIX];
__device__ float  g_xbar[NPIX];
__device__ float2 g_rbar[NPIX];

// ---------------------------------------------------------------------------
// Kernel A: tmp = TAU*eps2_adj(u2) in shared (with halo), then x-prox + r-prox
// + relaxation. On LAST iteration, only the x path, written to outx.
// ---------------------------------------------------------------------------
template<bool LAST>
__global__ void k_A(const float* __restrict__ y, const int* __restrict__ ths,
                    float* __restrict__ outx) {
    __shared__ float4 su[TH + 3][TW + 2];   // u2 rows -2..TH, cols -1..TW
    __shared__ float2 st[TH + 1][TW + 2];   // tmp rows -1..TH-1, cols -1..TW-1 (+pad)

    const int tx = threadIdx.x, ty = threadIdx.y;
    const int tid = ty * TW + tx;
    const int w0 = blockIdx.x * TW, h0 = blockIdx.y * TH, b = blockIdx.z;
    const float4* u2b = g_u2 + (size_t)b * HH * WW;

    // Load u2 tile with halo, zero-padded outside the image.
    #pragma unroll
    for (int idx = tid; idx < (TH + 3) * (TW + 2); idx += TW * TH) {
        int rr = idx / (TW + 2), cc = idx % (TW + 2);
        int gh = h0 + rr - 2, gw = w0 + cc - 1;
        float4 v = make_float4(0.f, 0.f, 0.f, 0.f);
        if (gh >= 0 && gh < HH && gw >= 0 && gw < WW) v = u2b[gh * WW + gw];
        su[rr][cc] = v;
    }
    __syncthreads();

    // tmp tile (1-halo up/left). Zero-pad + the u2 invariants (u2.y==0 at w=0,
    // u2.w==0 at h=H-1) make all boundary predicates unnecessary here.
    #pragma unroll
    for (int idx = tid; idx < (TH + 1) * (TW + 1); idx += TW * TH) {
        int R = idx / (TW + 1), C = idx % (TW + 1);
        float4 cen = su[R + 1][C];
        float4 dn  = su[R + 2][C];
        float4 up  = su[R][C];
        float4 rt  = su[R + 1][C + 1];
        st[R][C] = make_float2(TAUc * (cen.x - dn.x - rt.y + cen.y),
                               TAUc * (cen.z - rt.z - cen.w + up.w));
    }
    __syncthreads();

    const int h = h0 + ty, w = w0 + tx;
    const int i = (b * HH + h) * WW + w;

    float2 tc = st[ty + 1][tx + 1];
    float2 tl = st[ty + 1][tx];
    float2 tu = st[ty][tx + 1];

    float div = 0.f;
    if (w < WW - 1) div -= tc.x;
    if (w > 0)      div += tl.x;
    if (h < HH - 1) div -= tc.y;
    if (h > 0)      div += tu.y;

    float x2o = g_x2[i];
    float x = (x2o - div + TAUc * y[i]) * (1.f / (1.f + TAUc));
    float x2n = x2o + RHOc * (x - x2o);

    if (LAST) { outx[i] = x2n; return; }

    g_xbar[i] = 2.f * x - x2o;
    g_x2[i]   = x2n;

    float lam1 = 0.1f * (float)ths[0];
    float2 r2o = g_r2[i];
    float rvx = r2o.x + tc.x, rvy = r2o.y + tc.y;
    float nrm = sqrtf(rvx * rvx + rvy * rvy);
    float s = 1.f - 1.f / fmaxf(nrm * (1.f / (TAUc * lam1)), 1.f);
    float rx = rvx * s, ry = rvy * s;

    g_rbar[i] = make_float2(2.f * rx - r2o.x, 2.f * ry - r2o.y);
    g_r2[i]   = make_float2(r2o.x + RHOc * (rx - r2o.x),
                            r2o.y + RHOc * (ry - r2o.y));
}

// ---------------------------------------------------------------------------
// Kernel B: v = nabla2(xbar) - rbar in shared (with halo), then
// u = prox_sigma_g_conj(u2 + SIGMA*eps2(v)) + relaxation.
// FIRST iteration: xbar == y, rbar == 0, u2 == 0; also initializes x2=y, r2=0.
// ---------------------------------------------------------------------------
template<bool FIRST>
__global__ void k_B(const float* __restrict__ y, const int* __restrict__ ths) {
    __shared__ float  sx[TH + 3][TW + 3];   // xbar rows -1..TH+1, cols -1..TW (+pad)
    __shared__ float2 sv[TH + 2][TW + 2];   // v rows -1..TH, cols -1..TW-1 (+pad)

    const int tx = threadIdx.x, ty = threadIdx.y;
    const int tid = ty * TW + tx;
    const int w0 = blockIdx.x * TW, h0 = blockIdx.y * TH, b = blockIdx.z;
    const size_t boff = (size_t)b * HH * WW;
    const float* xb = FIRST ? (y + boff) : (g_xbar + boff);

    // Load xbar tile with halo (zero pad).
    #pragma unroll
    for (int idx = tid; idx < (TH + 3) * (TW + 2); idx += TW * TH) {
        int rr = idx / (TW + 2), cc = idx % (TW + 2);
        int gh = h0 + rr - 1, gw = w0 + cc - 1;
        float v = 0.f;
        if (gh >= 0 && gh < HH && gw >= 0 && gw < WW) v = xb[gh * WW + gw];
        sx[rr][cc] = v;
    }
    __syncthreads();

    // v tile (1-halo all around except right/bottom-by-1 per dependency).
    #pragma unroll
    for (int idx = tid; idx < (TH + 2) * (TW + 1); idx += TW * TH) {
        int R = idx / (TW + 1), C = idx % (TW + 1);
        int gh = h0 + R - 1, gw = w0 + C - 1;
        float2 v = make_float2(0.f, 0.f);
        if (gh >= 0 && gh < HH && gw >= 0 && gw < WW) {
            float xc = sx[R][C];
            float v0 = (gw < WW - 1) ? (sx[R][C + 1] - xc) : 0.f;
            float v1 = (gh < HH - 1) ? (sx[R + 1][C] - xc) : 0.f;
            if (!FIRST) {
                float2 rb = g_rbar[boff + gh * WW + gw];
                v0 -= rb.x; v1 -= rb.y;
            }
            v = make_float2(v0, v1);
        }
        sv[R][C] = v;
    }
    __syncthreads();

    const int h = h0 + ty, w = w0 + tx;
    const int i = (int)boff + h * WW + w;

    float2 vc = sv[ty + 1][tx + 1];
    float2 vu = sv[ty][tx + 1];
    float2 vl = sv[ty + 1][tx];
    float2 vd = sv[ty + 2][tx + 1];

    float G0 = vc.x - vu.x;                          // pad handles h==0
    float G1 = (w > 0) ? (vc.x - vl.x) : 0.f;
    float G2 = vc.y - vl.y;                          // pad handles w==0
    float G3 = (h < HH - 1) ? (vd.y - vc.y) : 0.f;

    float4 u2o = FIRST ? make_float4(0.f, 0.f, 0.f, 0.f) : g_u2[i];
    float u0 = u2o.x + SIGMAc * G0;
    float u1 = u2o.y + SIGMAc * G1;
    float u2c = u2o.z + SIGMAc * G2;
    float u3 = u2o.w + SIGMAc * G3;

    float lam2 = 0.15f * (float)ths[0];
    float nrm = sqrtf(u0 * u0 + u1 * u1 + u2c * u2c + u3 * u3);
    float sc = 1.f / fmaxf(nrm * (1.f / lam2), 1.f);
    u0 *= sc; u1 *= sc; u2c *= sc; u3 *= sc;

    g_u2[i] = make_float4(u2o.x + RHOc * (u0  - u2o.x),
                          u2o.y + RHOc * (u1  - u2o.y),
                          u2o.z + RHOc * (u2c - u2o.z),
                          u2o.w + RHOc * (u3  - u2o.w));

    if (FIRST) {
        // Iteration 1 closed form: x = xbar = y, r = rbar = 0.
        g_x2[i] = sx[ty + 1][tx + 1];
        g_r2[i] = make_float2(0.f, 0.f);
    }
}

extern "C" void kernel_launch(void* const* d_in, const int* in_sizes, int n_in,
                              void* d_out, int out_size) {
    const float* y   = (const float*)d_in[0];
    const int*   ths = (const int*)d_in[1];
    float*       out = (float*)d_out;

    dim3 blk(TW, TH, 1);
    dim3 grd(WW / TW, HH / TH, BB);

    // Iteration 1 (specialized: A is a no-op closed form)
    k_B<true><<<grd, blk>>>(y, ths);

    // Iterations 2..9
    for (int it = 1; it < 9; ++it) {
        k_A<false><<<grd, blk>>>(y, ths, nullptr);
        k_B<false><<<grd, blk>>>(y, ths);
    }

    // Iteration 10: only the x path matters; write straight to output.
    k_A<true><<<grd, blk>>>(y, ths, out);
}

// round 3
// speedup vs baseline: 1.2887x; 1.1838x over previous
#include <cuda_runtime.h>
#include <math.h>

#define BB 4
#define HH 512
#define WW 512
#define NPIX (BB*HH*WW)
#define TW 32
#define TH 8

#define TAUc   0.01f
#define RHOc   1.99f
#define SIGMAc 1.3888888888888888f   // 1/0.01/72

// Persistent state + scratch (allocation-free)
__device__ float  g_x2  [NPIX];
__device__ float2 g_r2  [NPIX];
__device__ float4 g_u2  [NPIX];
__device__ float  g_xbar[NPIX];
__device__ float2 g_rbar[NPIX];

// Zero-padded loads from the per-batch u2 plane.
static __device__ __forceinline__ float4 ld4(const float4* b, int h, int w) {
    if ((unsigned)h < HH && (unsigned)w < WW) return __ldg(b + h * WW + w);
    return make_float4(0.f, 0.f, 0.f, 0.f);
}
static __device__ __forceinline__ float2 ld2xy(const float4* b, int h, int w) {
    if ((unsigned)h < HH && (unsigned)w < WW)
        return __ldg((const float2*)(b + h * WW + w));   // (x,y), 8B aligned
    return make_float2(0.f, 0.f);
}
static __device__ __forceinline__ float lds(const float4* b, int h, int w, int comp) {
    if ((unsigned)h < HH && (unsigned)w < WW)
        return __ldg(((const float*)(b + h * WW + w)) + comp);
    return 0.f;
}

// ---------------------------------------------------------------------------
// Kernel A (direct-load): tmp = TAU*eps2_adj(u2) recomputed per thread at
// {p, left(comp0), up(comp1)}, then x-prox + r-prox + relaxation.
// On LAST iteration only the x path, written to outx.
// Uses zero-padding + the invariants u2.y==0 at w=0, u2.w==0 at h=H-1.
// ---------------------------------------------------------------------------
template<bool LAST>
__global__ void __launch_bounds__(TW*TH)
k_A(const float* __restrict__ y, const int* __restrict__ ths,
    float* __restrict__ outx) {
    const int w = blockIdx.x * TW + threadIdx.x;
    const int h = blockIdx.y * TH + threadIdx.y;
    const int b = blockIdx.z;
    const int i = (b * HH + h) * WW + w;
    const float4* u2b = g_u2 + (size_t)b * HH * WW;

    const float4 c   = __ldg(u2b + h * WW + w);       // u2(p)
    const float4 up  = ld4 (u2b, h - 1, w);           // u2(h-1,w)
    const float4 rt  = ld4 (u2b, h, w + 1);           // u2(h,w+1)
    const float2 lxy = ld2xy(u2b, h, w - 1);          // u2(h,w-1).xy
    const float  Xd  = lds(u2b, h + 1, w,     0);     // u2(h+1,w).x
    const float  Xdl = lds(u2b, h + 1, w - 1, 0);     // u2(h+1,w-1).x
    const float  Zur = lds(u2b, h - 1, w + 1, 2);     // u2(h-1,w+1).z
    const float  Wu2 = lds(u2b, h - 2, w,     3);     // u2(h-2,w).w

    // tmp components (zero-pad + invariants make these predicate-free)
    const float t0p = TAUc * (c.x   - Xd  - rt.y + c.y);     // tmp0(p)
    const float t1p = TAUc * (c.z   - rt.z - c.w + up.w);    // tmp1(p)
    const float t0l = TAUc * (lxy.x - Xdl - c.y  + lxy.y);   // tmp0(h,w-1)
    const float t1u = TAUc * (up.z  - Zur - up.w + Wu2);     // tmp1(h-1,w)

    float div = 0.f;
    if (w < WW - 1) div -= t0p;
    if (w > 0)      div += t0l;
    if (h < HH - 1) div -= t1p;
    if (h > 0)      div += t1u;

    const float x2o = __ldg(&g_x2[i]);
    const float x = (x2o - div + TAUc * __ldg(&y[i])) * (1.f / (1.f + TAUc));
    const float x2n = x2o + RHOc * (x - x2o);

    if (LAST) { outx[i] = x2n; return; }

    g_xbar[i] = 2.f * x - x2o;
    g_x2[i]   = x2n;

    const float lam1 = 0.1f * (float)__ldg(ths);
    const float2 r2o = __ldg(&g_r2[i]);
    const float rvx = r2o.x + t0p;
    const float rvy = r2o.y + t1p;
    const float nrm = sqrtf(rvx * rvx + rvy * rvy);
    const float s = 1.f - 1.f / fmaxf(nrm * (1.f / (TAUc * lam1)), 1.f);
    const float rx = rvx * s, ry = rvy * s;

    g_rbar[i] = make_float2(2.f * rx - r2o.x, 2.f * ry - r2o.y);
    g_r2[i]   = make_float2(r2o.x + RHOc * (rx - r2o.x),
                            r2o.y + RHOc * (ry - r2o.y));
}

// ---------------------------------------------------------------------------
// Kernel B (unchanged, it runs near the traffic floor):
// v = nabla2(xbar) - rbar in shared (with halo), then
// u = prox_sigma_g_conj(u2 + SIGMA*eps2(v)) + relaxation.
// FIRST iteration: xbar == y, rbar == 0, u2 == 0; also initializes x2=y, r2=0.
// ---------------------------------------------------------------------------
template<bool FIRST>
__global__ void __launch_bounds__(TW*TH)
k_B(const float* __restrict__ y, const int* __restrict__ ths) {
    __shared__ float  sx[TH + 3][TW + 3];   // xbar rows -1..TH+1, cols -1..TW (+pad)
    __shared__ float2 sv[TH + 2][TW + 2];   // v rows -1..TH, cols -1..TW-1 (+pad)

    const int tx = threadIdx.x, ty = threadIdx.y;
    const int tid = ty * TW + tx;
    const int w0 = blockIdx.x * TW, h0 = blockIdx.y * TH, b = blockIdx.z;
    const size_t boff = (size_t)b * HH * WW;
    const float* xb = FIRST ? (y + boff) : (g_xbar + boff);

    #pragma unroll
    for (int idx = tid; idx < (TH + 3) * (TW + 2); idx += TW * TH) {
        int rr = idx / (TW + 2), cc = idx % (TW + 2);
        int gh = h0 + rr - 1, gw = w0 + cc - 1;
        float v = 0.f;
        if (gh >= 0 && gh < HH && gw >= 0 && gw < WW) v = __ldg(xb + gh * WW + gw);
        sx[rr][cc] = v;
    }
    __syncthreads();

    #pragma unroll
    for (int idx = tid; idx < (TH + 2) * (TW + 1); idx += TW * TH) {
        int R = idx / (TW + 1), C = idx % (TW + 1);
        int gh = h0 + R - 1, gw = w0 + C - 1;
        float2 v = make_float2(0.f, 0.f);
        if (gh >= 0 && gh < HH && gw >= 0 && gw < WW) {
            float xc = sx[R][C];
            float v0 = (gw < WW - 1) ? (sx[R][C + 1] - xc) : 0.f;
            float v1 = (gh < HH - 1) ? (sx[R + 1][C] - xc) : 0.f;
            if (!FIRST) {
                float2 rb = __ldg(&g_rbar[boff + gh * WW + gw]);
                v0 -= rb.x; v1 -= rb.y;
            }
            v = make_float2(v0, v1);
        }
        sv[R][C] = v;
    }
    __syncthreads();

    const int h = h0 + ty, w = w0 + tx;
    const int i = (int)boff + h * WW + w;

    float2 vc = sv[ty + 1][tx + 1];
    float2 vu = sv[ty][tx + 1];
    float2 vl = sv[ty + 1][tx];
    float2 vd = sv[ty + 2][tx + 1];

    float G0 = vc.x - vu.x;
    float G1 = (w > 0) ? (vc.x - vl.x) : 0.f;
    float G2 = vc.y - vl.y;
    float G3 = (h < HH - 1) ? (vd.y - vc.y) : 0.f;

    float4 u2o = FIRST ? make_float4(0.f, 0.f, 0.f, 0.f) : __ldg(&g_u2[i]);
    float u0 = u2o.x + SIGMAc * G0;
    float u1 = u2o.y + SIGMAc * G1;
    float u2c = u2o.z + SIGMAc * G2;
    float u3 = u2o.w + SIGMAc * G3;

    float lam2 = 0.15f * (float)__ldg(ths);
    float nrm = sqrtf(u0 * u0 + u1 * u1 + u2c * u2c + u3 * u3);
    float sc = 1.f / fmaxf(nrm * (1.f / lam2), 1.f);
    u0 *= sc; u1 *= sc; u2c *= sc; u3 *= sc;

    g_u2[i] = make_float4(u2o.x + RHOc * (u0  - u2o.x),
                          u2o.y + RHOc * (u1  - u2o.y),
                          u2o.z + RHOc * (u2c - u2o.z),
                          u2o.w + RHOc * (u3  - u2o.w));

    if (FIRST) {
        g_x2[i] = sx[ty + 1][tx + 1];
        g_r2[i] = make_float2(0.f, 0.f);
    }
}

extern "C" void kernel_launch(void* const* d_in, const int* in_sizes, int n_in,
                              void* d_out, int out_size) {
    const float* y   = (const float*)d_in[0];
    const int*   ths = (const int*)d_in[1];
    float*       out = (float*)d_out;

    dim3 blk(TW, TH, 1);
    dim3 grd(WW / TW, HH / TH, BB);

    // Iteration 1 (specialized: A is a no-op closed form)
    k_B<true><<<grd, blk>>>(y, ths);

    // Iterations 2..9
    for (int it = 1; it < 9; ++it) {
        k_A<false><<<grd, blk>>>(y, ths, nullptr);
        k_B<false><<<grd, blk>>>(y, ths);
    }

    // Iteration 10: only the x path matters; write straight to output.
    k_A<true><<<grd, blk>>>(y, ths, out);
}